// round 2
// baseline (speedup 1.0000x reference)
#include <cuda_runtime.h>
#include <math.h>

// Problem constants (shapes fixed by setup_inputs)
#define NTOK   65536      // bs*W*H = 64*32*32
#define DIMZ   256
#define KC     1024
#define WH     1024       // W*H
#define BSZ    64
#define TM     32         // tokens per CTA
#define NTILES 2048       // NTOK / TM

// Output layout: [loss(1), z_to_decoder(NTOK*DIMZ), perplexity(1), avg_probs(KC), indices(NTOK)]
#define OFF_LOSS 0
#define OFF_Z    1
#define OFF_PERP 16777217
#define OFF_AVG  16777218
#define OFF_IDX  16778242

// dynamic smem layout (bytes)
#define SM_LOGITS 0                    // [32][1024] f32 = 131072
#define SM_A      131072               // GEMM1 CB stage [16][1024] = 65536 ; GEMM2 CB stage [32][256] = 32768
#define SM_RED    (131072 + 32768)     // [32][260] f32 = 33280 (zq partial / final)
#define SM_ZS     197632               // [16][32] f32 = 2048
#define SM_CNORM  199680               // [1024] f32
#define SM_PROB   203776               // [1024] f32
#define SM_ZNORM  207872               // [32] f32
#define SM_INVEY  208000               // [32] f32
#define SM_SCAL   208128               // scalars
#define SMEM_BYTES 208192

__device__ float g_cnorm[KC];
__device__ float g_prob_part[NTILES * KC];   // [tile][k]
__device__ float g_kldd_part[NTILES];
__device__ float g_sq_part[NTILES];

__device__ __forceinline__ float warp_sum(float v) {
#pragma unroll
    for (int o = 16; o; o >>= 1) v += __shfl_xor_sync(0xFFFFFFFFu, v, o);
    return v;
}

// ---------------------------------------------------------------------------
// Kernel 0: codebook row norms
// ---------------------------------------------------------------------------
__global__ void cnorm_kernel(const float* __restrict__ cb) {
    int c = blockIdx.x;           // 0..1023
    int t = threadIdx.x;          // 64 threads
    const float4* row = (const float4*)(cb + c * DIMZ);
    float4 v = row[t];            // 64*4 = 256
    float s = v.x * v.x + v.y * v.y + v.z * v.z + v.w * v.w;
    s = warp_sum(s);
    __shared__ float ws[2];
    if ((t & 31) == 0) ws[t >> 5] = s;
    __syncthreads();
    if (t == 0) g_cnorm[c] = ws[0] + ws[1];
}

// ---------------------------------------------------------------------------
// Main fused kernel: one CTA = 32 tokens
// ---------------------------------------------------------------------------
__global__ void __launch_bounds__(512, 1) vq_main_kernel(
    const float* __restrict__ z, const float* __restrict__ var,
    const float* __restrict__ cb, const float* __restrict__ gum,
    float* __restrict__ out)
{
    extern __shared__ char smem[];
    float* logits  = (float*)(smem + SM_LOGITS);   // [32][1024]; later holds unnormalized encodings
    float* cbs     = (float*)(smem + SM_A);
    float* red     = (float*)(smem + SM_RED);      // [32][260]
    float* zs      = (float*)(smem + SM_ZS);       // [16][32]
    float* cnorm_s = (float*)(smem + SM_CNORM);
    float* probsum = (float*)(smem + SM_PROB);
    float* znorm   = (float*)(smem + SM_ZNORM);
    float* invEy_s = (float*)(smem + SM_INVEY);
    float* scal    = (float*)(smem + SM_SCAL);

    const int tid  = threadIdx.x;
    const int tile = blockIdx.x;
    const int n0   = tile * TM;
    const int b0   = n0 >> 10;
    const int r0   = n0 & 1023;
    const float* zbase = z + (long)b0 * (DIMZ * WH) + r0;
    const float prec = 1.0f / fmaxf(var[0], 1e-10f);

    // preamble
    probsum[tid] = 0.0f; probsum[tid + 512] = 0.0f;
    cnorm_s[tid] = g_cnorm[tid]; cnorm_s[tid + 512] = g_cnorm[tid + 512];
    if (tid < 32) znorm[tid] = 0.0f;
    if (tid == 0) scal[0] = 0.0f;

    // ======================= GEMM1: dot[32][1024] =======================
    const int tg  = tid >> 6;       // 0..7 (token group of 4)
    const int cg  = tid & 63;       // 0..63 (code group of 16)
    const int tg4 = tg * 4;
    float acc[4][16];
#pragma unroll
    for (int i = 0; i < 4; i++)
#pragma unroll
        for (int j = 0; j < 16; j++) acc[i][j] = 0.0f;

    const int lkk = tid >> 5, ltt = tid & 31;

#pragma unroll 1
    for (int d0 = 0; d0 < DIMZ; d0 += 16) {
        __syncthreads();
        // stage Z chunk [16][32] (coalesced rows of 32 tokens)
        zs[tid] = zbase[(long)(d0 + lkk) * WH + ltt];
        // stage CB chunk transposed: cbs[kk][code] = cb[code][d0+kk]
#pragma unroll
        for (int h = 0; h < 2; h++) {
            int c = tid + h * 512;
            const float4* grow = (const float4*)(cb + (long)c * DIMZ + d0);
#pragma unroll
            for (int q = 0; q < 4; q++) {
                float4 v = grow[q];
                cbs[(q * 4 + 0) * 1024 + c] = v.x;
                cbs[(q * 4 + 1) * 1024 + c] = v.y;
                cbs[(q * 4 + 2) * 1024 + c] = v.z;
                cbs[(q * 4 + 3) * 1024 + c] = v.w;
            }
        }
        __syncthreads();
        if (tid < 32) {
            float s = 0.0f;
#pragma unroll
            for (int kk = 0; kk < 16; kk++) { float v = zs[kk * 32 + tid]; s += v * v; }
            znorm[tid] += s;
        }
#pragma unroll
        for (int kk = 0; kk < 16; kk++) {
            float a0 = zs[kk * 32 + tg4 + 0];
            float a1 = zs[kk * 32 + tg4 + 1];
            float a2 = zs[kk * 32 + tg4 + 2];
            float a3 = zs[kk * 32 + tg4 + 3];
            const float4* br = (const float4*)(cbs + kk * 1024 + cg * 16);
#pragma unroll
            for (int q = 0; q < 4; q++) {
                float4 b = br[q];
                acc[0][q*4+0] += a0 * b.x; acc[0][q*4+1] += a0 * b.y;
                acc[0][q*4+2] += a0 * b.z; acc[0][q*4+3] += a0 * b.w;
                acc[1][q*4+0] += a1 * b.x; acc[1][q*4+1] += a1 * b.y;
                acc[1][q*4+2] += a1 * b.z; acc[1][q*4+3] += a1 * b.w;
                acc[2][q*4+0] += a2 * b.x; acc[2][q*4+1] += a2 * b.y;
                acc[2][q*4+2] += a2 * b.z; acc[2][q*4+3] += a2 * b.w;
                acc[3][q*4+0] += a3 * b.x; acc[3][q*4+1] += a3 * b.y;
                acc[3][q*4+2] += a3 * b.z; acc[3][q*4+3] += a3 * b.w;
            }
        }
    }
    __syncthreads();

    // logit = prec*dot - 0.5*prec*(||z||^2 + ||c||^2)
    const float hp = 0.5f * prec;
#pragma unroll
    for (int i = 0; i < 4; i++) {
        int tt = tg4 + i;
        float zn = znorm[tt];
#pragma unroll
        for (int j = 0; j < 16; j++) {
            int k = cg * 16 + j;
            logits[tt * 1024 + k] = prec * acc[i][j] - hp * (zn + cnorm_s[k]);
        }
    }
    __syncthreads();

    // ======================= Phase 2: dual softmax per token =======================
    const int warp = tid >> 5, lane = tid & 31;
    float kldd_w = 0.0f;
#pragma unroll 1
    for (int rep = 0; rep < 2; rep++) {
        int t = warp * 2 + rep;
        int n = n0 + t;
        const float* gr = gum + (long)n * KC;
        float l[32], yv[32];
        float bv = -1e30f, my = -1e30f; int bk = 0;
#pragma unroll
        for (int j = 0; j < 32; j++) {
            int k = lane + j * 32;
            float lv = logits[t * 1024 + k];
            l[j] = lv;
            float u = gr[k];
            float g = -__logf(-__logf(u + 1e-10f) + 1e-10f);
            float y = (lv + g) * 2.0f;          // /T, T=0.5
            yv[j] = y;
            if (lv > bv) { bv = lv; bk = k; }   // k strictly increasing -> first max kept
            my = fmaxf(my, y);
        }
        // warp argmax (lowest index on tie) + max of y
#pragma unroll
        for (int o = 16; o; o >>= 1) {
            float ov = __shfl_xor_sync(0xFFFFFFFFu, bv, o);
            int   ok = __shfl_xor_sync(0xFFFFFFFFu, bk, o);
            if (ov > bv || (ov == bv && ok < bk)) { bv = ov; bk = ok; }
            my = fmaxf(my, __shfl_xor_sync(0xFFFFFFFFu, my, o));
        }
        float m = bv;
        float E = 0.0f, F = 0.0f, Ey = 0.0f;
#pragma unroll
        for (int j = 0; j < 32; j++) {
            float d = l[j] - m;
            float e = __expf(d);
            E += e; F += e * d;
            l[j] = e;                           // cache exp for probsum pass
            float ey = __expf(yv[j] - my);
            Ey += ey;
            yv[j] = ey;
        }
        E = warp_sum(E); F = warp_sum(F); Ey = warp_sum(Ey);
        float invE = 1.0f / E;
        kldd_w += F * invE - __logf(E);      // sum_k p*logp for token t
        if (lane == 0) {
            out[OFF_IDX + n] = (float)bk;
            invEy_s[t] = 1.0f / Ey;
        }
#pragma unroll
        for (int j = 0; j < 32; j++) {
            int k = lane + j * 32;
            atomicAdd(&probsum[k], l[j] * invE);
            logits[t * 1024 + k] = yv[j];     // unnormalized encodings
        }
    }
    if (lane == 0) atomicAdd(&scal[0], kldd_w);
    __syncthreads();

    // export deterministic partials
    g_prob_part[tile * KC + tid]       = probsum[tid];
    g_prob_part[tile * KC + tid + 512] = probsum[tid + 512];
    if (tid == 0) g_kldd_part[tile] = scal[0];

    // ======================= GEMM2: zq[32][256] = enc @ CB (split-k x2) =======================
    const int slice = tid >> 8;           // 0,1
    const int t2    = (tid & 255) >> 5;   // 0..7
    const int dg    = tid & 31;
    float acc2[4][8];
#pragma unroll
    for (int i = 0; i < 4; i++)
#pragma unroll
        for (int j = 0; j < 8; j++) acc2[i][j] = 0.0f;

#pragma unroll 1
    for (int k0 = 0; k0 < KC; k0 += 32) {
        __syncthreads();
        {   // stage cb rows k0..k0+31 (32KB, fully coalesced)
            const float4* gsrc = (const float4*)(cb + (long)k0 * DIMZ);
            float4* dst = (float4*)cbs;
#pragma unroll
            for (int i = 0; i < 4; i++) dst[tid + i * 512] = gsrc[tid + i * 512];
        }
        __syncthreads();
        const int kb = slice * 16;
#pragma unroll
        for (int kk = 0; kk < 16; kk++) {
            int k = kb + kk;
            float a0 = logits[(t2 * 4 + 0) * 1024 + k0 + k];
            float a1 = logits[(t2 * 4 + 1) * 1024 + k0 + k];
            float a2 = logits[(t2 * 4 + 2) * 1024 + k0 + k];
            float a3 = logits[(t2 * 4 + 3) * 1024 + k0 + k];
            const float4* br = (const float4*)(cbs + k * DIMZ + dg * 8);
            float4 b0 = br[0], b1 = br[1];
            acc2[0][0]+=a0*b0.x; acc2[0][1]+=a0*b0.y; acc2[0][2]+=a0*b0.z; acc2[0][3]+=a0*b0.w;
            acc2[0][4]+=a0*b1.x; acc2[0][5]+=a0*b1.y; acc2[0][6]+=a0*b1.z; acc2[0][7]+=a0*b1.w;
            acc2[1][0]+=a1*b0.x; acc2[1][1]+=a1*b0.y; acc2[1][2]+=a1*b0.z; acc2[1][3]+=a1*b0.w;
            acc2[1][4]+=a1*b1.x; acc2[1][5]+=a1*b1.y; acc2[1][6]+=a1*b1.z; acc2[1][7]+=a1*b1.w;
            acc2[2][0]+=a2*b0.x; acc2[2][1]+=a2*b0.y; acc2[2][2]+=a2*b0.z; acc2[2][3]+=a2*b0.w;
            acc2[2][4]+=a2*b1.x; acc2[2][5]+=a2*b1.y; acc2[2][6]+=a2*b1.z; acc2[2][7]+=a2*b1.w;
            acc2[3][0]+=a3*b0.x; acc2[3][1]+=a3*b0.y; acc2[3][2]+=a3*b0.z; acc2[3][3]+=a3*b0.w;
            acc2[3][4]+=a3*b1.x; acc2[3][5]+=a3*b1.y; acc2[3][6]+=a3*b1.z; acc2[3][7]+=a3*b1.w;
        }
    }
    __syncthreads();
    if (slice == 1) {
#pragma unroll
        for (int i = 0; i < 4; i++) {
            float4* p = (float4*)(red + (t2 * 4 + i) * 260 + dg * 8);
            p[0] = make_float4(acc2[i][0], acc2[i][1], acc2[i][2], acc2[i][3]);
            p[1] = make_float4(acc2[i][4], acc2[i][5], acc2[i][6], acc2[i][7]);
        }
    }
    __syncthreads();
    if (slice == 0) {
#pragma unroll
        for (int i = 0; i < 4; i++) {
            int tt = t2 * 4 + i;
            float sc = invEy_s[tt];
            float4* p = (float4*)(red + tt * 260 + dg * 8);
            float4 a = p[0], b = p[1];
            a.x = (a.x + acc2[i][0]) * sc; a.y = (a.y + acc2[i][1]) * sc;
            a.z = (a.z + acc2[i][2]) * sc; a.w = (a.w + acc2[i][3]) * sc;
            b.x = (b.x + acc2[i][4]) * sc; b.y = (b.y + acc2[i][5]) * sc;
            b.z = (b.z + acc2[i][6]) * sc; b.w = (b.w + acc2[i][7]) * sc;
            p[0] = a; p[1] = b;
        }
    }
    __syncthreads();

    // epilogue: write z_to_decoder (native layout, coalesced) + sum of squared residuals
    float sq = 0.0f;
    float* outz = out + OFF_Z + (long)b0 * (DIMZ * WH) + r0;
#pragma unroll
    for (int i = 0; i < 16; i++) {
        int idx = tid + i * 512;
        int d = idx >> 5, tt = idx & 31;
        float zq = red[tt * 260 + d];
        float zv = zbase[(long)d * WH + tt];
        float df = zv - zq;
        sq += df * df;
        outz[(long)d * WH + tt] = zq;
    }
    sq = warp_sum(sq);
    if (lane == 0) probsum[warp] = sq;   // probsum region is free now
    __syncthreads();
    if (tid == 0) {
        float s = 0.0f;
#pragma unroll
        for (int w = 0; w < 16; w++) s += probsum[w];
        g_sq_part[tile] = s;
    }
}

// ---------------------------------------------------------------------------
// Finalize 1: avg_probs
// ---------------------------------------------------------------------------
__global__ void f1_kernel(float* __restrict__ out) {
    int k = blockIdx.x;            // 0..1023
    int t = threadIdx.x;           // 256
    float s = 0.0f;
#pragma unroll
    for (int i = 0; i < NTILES / 256; i++)
        s += g_prob_part[(t + i * 256) * KC + k];
    s = warp_sum(s);
    __shared__ float sd[8];
    if ((t & 31) == 0) sd[t >> 5] = s;
    __syncthreads();
    if (t == 0) {
        float tot = 0.0f;
#pragma unroll
        for (int w = 0; w < 8; w++) tot += sd[w];
        out[OFF_AVG + k] = tot / (float)NTOK;
    }
}

// ---------------------------------------------------------------------------
// Finalize 2: loss + perplexity
// ---------------------------------------------------------------------------
__global__ void f2_kernel(const float* __restrict__ var, float* __restrict__ out) {
    int t = threadIdx.x;           // 1024
    __shared__ float sd[32];
    __shared__ float res[3];

    float a  = out[OFF_AVG + t];
    float pe = a * __logf(a + 1e-7f);
    float kd = g_kldd_part[t] + g_kldd_part[t + 1024];
    float sq = g_sq_part[t]   + g_sq_part[t + 1024];

    float vals[3] = {pe, kd, sq};
#pragma unroll
    for (int r = 0; r < 3; r++) {
        float v = warp_sum(vals[r]);
        __syncthreads();
        if ((t & 31) == 0) sd[t >> 5] = v;
        __syncthreads();
        if (t == 0) {
            float tot = 0.0f;
#pragma unroll
            for (int w = 0; w < 32; w++) tot += sd[w];
            res[r] = tot;
        }
    }
    __syncthreads();
    if (t == 0) {
        float ps = 1.0f / fmaxf(var[0], 1e-10f);   // sum(var) == var[0], numel 1
        float loss = res[1] / (float)BSZ + res[2] * 0.5f * ps / (float)BSZ;
        out[OFF_LOSS] = loss;
        out[OFF_PERP] = __expf(-res[0]);
    }
}

// ---------------------------------------------------------------------------
extern "C" void kernel_launch(void* const* d_in, const int* in_sizes, int n_in,
                              void* d_out, int out_size) {
    // identify inputs by size (robust to metadata ordering)
    const float *z = nullptr, *var = nullptr, *cb = nullptr, *gum = nullptr;
    for (int i = 0; i < n_in; i++) {
        switch (in_sizes[i]) {
            case NTOK * DIMZ:  z   = (const float*)d_in[i]; break;  // 16777216
            case 1:            var = (const float*)d_in[i]; break;
            case KC * DIMZ:    cb  = (const float*)d_in[i]; break;  // 262144
            default:           gum = (const float*)d_in[i]; break;  // 67108864
        }
    }
    float* out = (float*)d_out;

    cudaFuncSetAttribute(vq_main_kernel,
                         cudaFuncAttributeMaxDynamicSharedMemorySize, SMEM_BYTES);

    cnorm_kernel<<<KC, 64>>>(cb);
    vq_main_kernel<<<NTILES, 512, SMEM_BYTES>>>(z, var, cb, gum, out);
    f1_kernel<<<KC, 256>>>(out);
    f2_kernel<<<1, 1024>>>(var, out);
}

// round 5
// speedup vs baseline: 1.0002x; 1.0002x over previous
#include <cuda_runtime.h>
#include <math.h>

// Problem constants (shapes fixed by setup_inputs)
#define NTOK   65536      // bs*W*H = 64*32*32
#define DIMZ   256
#define KC     1024
#define WH     1024       // W*H
#define BSZ    64
#define TM     32         // tokens per CTA
#define NTILES 2048       // NTOK / TM

// Output layout: [loss(1), z_to_decoder(NTOK*DIMZ), perplexity(1), avg_probs(KC), indices(NTOK)]
#define OFF_LOSS 0
#define OFF_Z    1
#define OFF_PERP 16777217
#define OFF_AVG  16777218
#define OFF_IDX  16778242

// dynamic smem layout (bytes)
#define SM_LOGITS 0                    // [32][1024] f32 = 131072
#define SM_A      131072               // GEMM1 CB stage [16][1024] = 65536 ; GEMM2 CB stage [32][256] = 32768
#define SM_RED    (131072 + 32768)     // [32][260] f32 = 33280 (zq partial / final)
#define SM_ZS     197632               // [16][32] f32 = 2048
#define SM_CNORM  199680               // [1024] f32
#define SM_PROB   203776               // [1024] f32
#define SM_ZNORM  207872               // [32] f32
#define SM_INVEY  208000               // [32] f32
#define SM_SCAL   208128               // scalars
#define SMEM_BYTES 208192

__device__ float g_cnorm[KC];
__device__ float g_prob_part[NTILES * KC];   // [tile][k]
__device__ float g_kldd_part[NTILES];
__device__ float g_sq_part[NTILES];

__device__ __forceinline__ float warp_sum(float v) {
#pragma unroll
    for (int o = 16; o; o >>= 1) v += __shfl_xor_sync(0xFFFFFFFFu, v, o);
    return v;
}

// ---------------------------------------------------------------------------
// Kernel 0: codebook row norms
// ---------------------------------------------------------------------------
__global__ void cnorm_kernel(const float* __restrict__ cb) {
    int c = blockIdx.x;           // 0..1023
    int t = threadIdx.x;          // 64 threads
    const float4* row = (const float4*)(cb + c * DIMZ);
    float4 v = row[t];            // 64*4 = 256
    float s = v.x * v.x + v.y * v.y + v.z * v.z + v.w * v.w;
    s = warp_sum(s);
    __shared__ float ws[2];
    if ((t & 31) == 0) ws[t >> 5] = s;
    __syncthreads();
    if (t == 0) g_cnorm[c] = ws[0] + ws[1];
}

// ---------------------------------------------------------------------------
// Main fused kernel: one CTA = 32 tokens
// ---------------------------------------------------------------------------
__global__ void __launch_bounds__(512, 1) vq_main_kernel(
    const float* __restrict__ z, const float* __restrict__ var,
    const float* __restrict__ cb, const float* __restrict__ gum,
    float* __restrict__ out)
{
    extern __shared__ char smem[];
    float* logits  = (float*)(smem + SM_LOGITS);   // [32][1024]; later holds unnormalized encodings
    float* cbs     = (float*)(smem + SM_A);
    float* red     = (float*)(smem + SM_RED);      // [32][260]
    float* zs      = (float*)(smem + SM_ZS);       // [16][32]
    float* cnorm_s = (float*)(smem + SM_CNORM);
    float* probsum = (float*)(smem + SM_PROB);
    float* znorm   = (float*)(smem + SM_ZNORM);
    float* invEy_s = (float*)(smem + SM_INVEY);
    float* scal    = (float*)(smem + SM_SCAL);

    const int tid  = threadIdx.x;
    const int tile = blockIdx.x;
    const int n0   = tile * TM;
    const int b0   = n0 >> 10;
    const int r0   = n0 & 1023;
    const float* zbase = z + (long)b0 * (DIMZ * WH) + r0;
    const float prec = 1.0f / fmaxf(var[0], 1e-10f);

    // preamble
    probsum[tid] = 0.0f; probsum[tid + 512] = 0.0f;
    cnorm_s[tid] = g_cnorm[tid]; cnorm_s[tid + 512] = g_cnorm[tid + 512];
    if (tid < 32) znorm[tid] = 0.0f;
    if (tid == 0) scal[0] = 0.0f;

    // ======================= GEMM1: dot[32][1024] =======================
    const int tg  = tid >> 6;       // 0..7 (token group of 4)
    const int cg  = tid & 63;       // 0..63 (code group of 16)
    const int tg4 = tg * 4;
    float acc[4][16];
#pragma unroll
    for (int i = 0; i < 4; i++)
#pragma unroll
        for (int j = 0; j < 16; j++) acc[i][j] = 0.0f;

    const int lkk = tid >> 5, ltt = tid & 31;

#pragma unroll 1
    for (int d0 = 0; d0 < DIMZ; d0 += 16) {
        __syncthreads();
        // stage Z chunk [16][32] (coalesced rows of 32 tokens)
        zs[tid] = zbase[(long)(d0 + lkk) * WH + ltt];
        // stage CB chunk transposed: cbs[kk][code] = cb[code][d0+kk]
#pragma unroll
        for (int h = 0; h < 2; h++) {
            int c = tid + h * 512;
            const float4* grow = (const float4*)(cb + (long)c * DIMZ + d0);
#pragma unroll
            for (int q = 0; q < 4; q++) {
                float4 v = grow[q];
                cbs[(q * 4 + 0) * 1024 + c] = v.x;
                cbs[(q * 4 + 1) * 1024 + c] = v.y;
                cbs[(q * 4 + 2) * 1024 + c] = v.z;
                cbs[(q * 4 + 3) * 1024 + c] = v.w;
            }
        }
        __syncthreads();
        if (tid < 32) {
            float s = 0.0f;
#pragma unroll
            for (int kk = 0; kk < 16; kk++) { float v = zs[kk * 32 + tid]; s += v * v; }
            znorm[tid] += s;
        }
#pragma unroll
        for (int kk = 0; kk < 16; kk++) {
            float a0 = zs[kk * 32 + tg4 + 0];
            float a1 = zs[kk * 32 + tg4 + 1];
            float a2 = zs[kk * 32 + tg4 + 2];
            float a3 = zs[kk * 32 + tg4 + 3];
            const float4* br = (const float4*)(cbs + kk * 1024 + cg * 16);
#pragma unroll
            for (int q = 0; q < 4; q++) {
                float4 b = br[q];
                acc[0][q*4+0] += a0 * b.x; acc[0][q*4+1] += a0 * b.y;
                acc[0][q*4+2] += a0 * b.z; acc[0][q*4+3] += a0 * b.w;
                acc[1][q*4+0] += a1 * b.x; acc[1][q*4+1] += a1 * b.y;
                acc[1][q*4+2] += a1 * b.z; acc[1][q*4+3] += a1 * b.w;
                acc[2][q*4+0] += a2 * b.x; acc[2][q*4+1] += a2 * b.y;
                acc[2][q*4+2] += a2 * b.z; acc[2][q*4+3] += a2 * b.w;
                acc[3][q*4+0] += a3 * b.x; acc[3][q*4+1] += a3 * b.y;
                acc[3][q*4+2] += a3 * b.z; acc[3][q*4+3] += a3 * b.w;
            }
        }
    }
    __syncthreads();

    // logit = prec*dot - 0.5*prec*(||z||^2 + ||c||^2)
    const float hp = 0.5f * prec;
#pragma unroll
    for (int i = 0; i < 4; i++) {
        int tt = tg4 + i;
        float zn = znorm[tt];
#pragma unroll
        for (int j = 0; j < 16; j++) {
            int k = cg * 16 + j;
            logits[tt * 1024 + k] = prec * acc[i][j] - hp * (zn + cnorm_s[k]);
        }
    }
    __syncthreads();

    // ======================= Phase 2: dual softmax per token =======================
    const int warp = tid >> 5, lane = tid & 31;
    float kldd_w = 0.0f;
#pragma unroll 1
    for (int rep = 0; rep < 2; rep++) {
        int t = warp * 2 + rep;
        int n = n0 + t;
        const float* gr = gum + (long)n * KC;
        float l[32], yv[32];
        float bv = -1e30f, my = -1e30f; int bk = 0;
#pragma unroll
        for (int j = 0; j < 32; j++) {
            int k = lane + j * 32;
            float lv = logits[t * 1024 + k];
            l[j] = lv;
            float u = gr[k];
            float g = -__logf(-__logf(u + 1e-10f) + 1e-10f);
            float y = (lv + g) * 2.0f;          // /T, T=0.5
            yv[j] = y;
            if (lv > bv) { bv = lv; bk = k; }   // k strictly increasing -> first max kept
            my = fmaxf(my, y);
        }
        // warp argmax (lowest index on tie) + max of y
#pragma unroll
        for (int o = 16; o; o >>= 1) {
            float ov = __shfl_xor_sync(0xFFFFFFFFu, bv, o);
            int   ok = __shfl_xor_sync(0xFFFFFFFFu, bk, o);
            if (ov > bv || (ov == bv && ok < bk)) { bv = ov; bk = ok; }
            my = fmaxf(my, __shfl_xor_sync(0xFFFFFFFFu, my, o));
        }
        float m = bv;
        float E = 0.0f, F = 0.0f, Ey = 0.0f;
#pragma unroll
        for (int j = 0; j < 32; j++) {
            float d = l[j] - m;
            float e = __expf(d);
            E += e; F += e * d;
            l[j] = e;                           // cache exp for probsum pass
            float ey = __expf(yv[j] - my);
            Ey += ey;
            yv[j] = ey;
        }
        E = warp_sum(E); F = warp_sum(F); Ey = warp_sum(Ey);
        float invE = 1.0f / E;
        kldd_w += F * invE - __logf(E);      // sum_k p*logp for token t
        if (lane == 0) {
            out[OFF_IDX + n] = (float)bk;
            invEy_s[t] = 1.0f / Ey;
        }
#pragma unroll
        for (int j = 0; j < 32; j++) {
            int k = lane + j * 32;
            atomicAdd(&probsum[k], l[j] * invE);
            logits[t * 1024 + k] = yv[j];     // unnormalized encodings
        }
    }
    if (lane == 0) atomicAdd(&scal[0], kldd_w);
    __syncthreads();

    // export deterministic partials
    g_prob_part[tile * KC + tid]       = probsum[tid];
    g_prob_part[tile * KC + tid + 512] = probsum[tid + 512];
    if (tid == 0) g_kldd_part[tile] = scal[0];

    // ======================= GEMM2: zq[32][256] = enc @ CB (split-k x2) =======================
    const int slice = tid >> 8;           // 0,1
    const int t2    = (tid & 255) >> 5;   // 0..7
    const int dg    = tid & 31;
    float acc2[4][8];
#pragma unroll
    for (int i = 0; i < 4; i++)
#pragma unroll
        for (int j = 0; j < 8; j++) acc2[i][j] = 0.0f;

#pragma unroll 1
    for (int k0 = 0; k0 < KC; k0 += 32) {
        __syncthreads();
        {   // stage cb rows k0..k0+31 (32KB, fully coalesced)
            const float4* gsrc = (const float4*)(cb + (long)k0 * DIMZ);
            float4* dst = (float4*)cbs;
#pragma unroll
            for (int i = 0; i < 4; i++) dst[tid + i * 512] = gsrc[tid + i * 512];
        }
        __syncthreads();
        const int kb = slice * 16;
#pragma unroll
        for (int kk = 0; kk < 16; kk++) {
            int k = kb + kk;
            float a0 = logits[(t2 * 4 + 0) * 1024 + k0 + k];
            float a1 = logits[(t2 * 4 + 1) * 1024 + k0 + k];
            float a2 = logits[(t2 * 4 + 2) * 1024 + k0 + k];
            float a3 = logits[(t2 * 4 + 3) * 1024 + k0 + k];
            const float4* br = (const float4*)(cbs + k * DIMZ + dg * 8);
            float4 b0 = br[0], b1 = br[1];
            acc2[0][0]+=a0*b0.x; acc2[0][1]+=a0*b0.y; acc2[0][2]+=a0*b0.z; acc2[0][3]+=a0*b0.w;
            acc2[0][4]+=a0*b1.x; acc2[0][5]+=a0*b1.y; acc2[0][6]+=a0*b1.z; acc2[0][7]+=a0*b1.w;
            acc2[1][0]+=a1*b0.x; acc2[1][1]+=a1*b0.y; acc2[1][2]+=a1*b0.z; acc2[1][3]+=a1*b0.w;
            acc2[1][4]+=a1*b1.x; acc2[1][5]+=a1*b1.y; acc2[1][6]+=a1*b1.z; acc2[1][7]+=a1*b1.w;
            acc2[2][0]+=a2*b0.x; acc2[2][1]+=a2*b0.y; acc2[2][2]+=a2*b0.z; acc2[2][3]+=a2*b0.w;
            acc2[2][4]+=a2*b1.x; acc2[2][5]+=a2*b1.y; acc2[2][6]+=a2*b1.z; acc2[2][7]+=a2*b1.w;
            acc2[3][0]+=a3*b0.x; acc2[3][1]+=a3*b0.y; acc2[3][2]+=a3*b0.z; acc2[3][3]+=a3*b0.w;
            acc2[3][4]+=a3*b1.x; acc2[3][5]+=a3*b1.y; acc2[3][6]+=a3*b1.z; acc2[3][7]+=a3*b1.w;
        }
    }
    __syncthreads();
    if (slice == 1) {
#pragma unroll
        for (int i = 0; i < 4; i++) {
            float4* p = (float4*)(red + (t2 * 4 + i) * 260 + dg * 8);
            p[0] = make_float4(acc2[i][0], acc2[i][1], acc2[i][2], acc2[i][3]);
            p[1] = make_float4(acc2[i][4], acc2[i][5], acc2[i][6], acc2[i][7]);
        }
    }
    __syncthreads();
    if (slice == 0) {
#pragma unroll
        for (int i = 0; i < 4; i++) {
            int tt = t2 * 4 + i;
            float sc = invEy_s[tt];
            float4* p = (float4*)(red + tt * 260 + dg * 8);
            float4 a = p[0], b = p[1];
            a.x = (a.x + acc2[i][0]) * sc; a.y = (a.y + acc2[i][1]) * sc;
            a.z = (a.z + acc2[i][2]) * sc; a.w = (a.w + acc2[i][3]) * sc;
            b.x = (b.x + acc2[i][4]) * sc; b.y = (b.y + acc2[i][5]) * sc;
            b.z = (b.z + acc2[i][6]) * sc; b.w = (b.w + acc2[i][7]) * sc;
            p[0] = a; p[1] = b;
        }
    }
    __syncthreads();

    // epilogue: write z_to_decoder (native layout, coalesced) + sum of squared residuals
    float sq = 0.0f;
    float* outz = out + OFF_Z + (long)b0 * (DIMZ * WH) + r0;
#pragma unroll
    for (int i = 0; i < 16; i++) {
        int idx = tid + i * 512;
        int d = idx >> 5, tt = idx & 31;
        float zq = red[tt * 260 + d];
        float zv = zbase[(long)d * WH + tt];
        float df = zv - zq;
        sq += df * df;
        outz[(long)d * WH + tt] = zq;
    }
    sq = warp_sum(sq);
    if (lane == 0) probsum[warp] = sq;   // probsum region is free now
    __syncthreads();
    if (tid == 0) {
        float s = 0.0f;
#pragma unroll
        for (int w = 0; w < 16; w++) s += probsum[w];
        g_sq_part[tile] = s;
    }
}

// ---------------------------------------------------------------------------
// Finalize 1: avg_probs
// ---------------------------------------------------------------------------
__global__ void f1_kernel(float* __restrict__ out) {
    int k = blockIdx.x;            // 0..1023
    int t = threadIdx.x;           // 256
    float s = 0.0f;
#pragma unroll
    for (int i = 0; i < NTILES / 256; i++)
        s += g_prob_part[(t + i * 256) * KC + k];
    s = warp_sum(s);
    __shared__ float sd[8];
    if ((t & 31) == 0) sd[t >> 5] = s;
    __syncthreads();
    if (t == 0) {
        float tot = 0.0f;
#pragma unroll
        for (int w = 0; w < 8; w++) tot += sd[w];
        out[OFF_AVG + k] = tot / (float)NTOK;
    }
}

// ---------------------------------------------------------------------------
// Finalize 2: loss + perplexity
// ---------------------------------------------------------------------------
__global__ void f2_kernel(const float* __restrict__ var, float* __restrict__ out) {
    int t = threadIdx.x;           // 1024
    __shared__ float sd[32];
    __shared__ float res[3];

    float a  = out[OFF_AVG + t];
    float pe = a * __logf(a + 1e-7f);
    float kd = g_kldd_part[t] + g_kldd_part[t + 1024];
    float sq = g_sq_part[t]   + g_sq_part[t + 1024];

    float vals[3] = {pe, kd, sq};
#pragma unroll
    for (int r = 0; r < 3; r++) {
        float v = warp_sum(vals[r]);
        __syncthreads();
        if ((t & 31) == 0) sd[t >> 5] = v;
        __syncthreads();
        if (t == 0) {
            float tot = 0.0f;
#pragma unroll
            for (int w = 0; w < 32; w++) tot += sd[w];
            res[r] = tot;
        }
    }
    __syncthreads();
    if (t == 0) {
        float ps = 1.0f / fmaxf(var[0], 1e-10f);   // sum(var) == var[0], numel 1
        float loss = res[1] / (float)BSZ + res[2] * 0.5f * ps / (float)BSZ;
        out[OFF_LOSS] = loss;
        out[OFF_PERP] = __expf(-res[0]);
    }
}

// ---------------------------------------------------------------------------
extern "C" void kernel_launch(void* const* d_in, const int* in_sizes, int n_in,
                              void* d_out, int out_size) {
    // identify inputs by size (robust to metadata ordering)
    const float *z = nullptr, *var = nullptr, *cb = nullptr, *gum = nullptr;
    for (int i = 0; i < n_in; i++) {
        switch (in_sizes[i]) {
            case NTOK * DIMZ:  z   = (const float*)d_in[i]; break;  // 16777216
            case 1:            var = (const float*)d_in[i]; break;
            case KC * DIMZ:    cb  = (const float*)d_in[i]; break;  // 262144
            default:           gum = (const float*)d_in[i]; break;  // 67108864
        }
    }
    float* out = (float*)d_out;

    cudaFuncSetAttribute(vq_main_kernel,
                         cudaFuncAttributeMaxDynamicSharedMemorySize, SMEM_BYTES);

    cnorm_kernel<<<KC, 64>>>(cb);
    vq_main_kernel<<<NTILES, 512, SMEM_BYTES>>>(z, var, cb, gum, out);
    f1_kernel<<<KC, 256>>>(out);
    f2_kernel<<<1, 1024>>>(var, out);
}